// round 4
// baseline (speedup 1.0000x reference)
#include <cuda_runtime.h>

#define TT   1000
#define NCH  4096

// scratch (no cudaMalloc allowed)
__device__ float g_seq[NCH * TT];     // LSTM input, [chain][t], 16 MB
__device__ float g_feat[NCH * 32];    // [chain][ h_fwd(16) | h_bwd(16) ]

typedef unsigned long long u64;

// ---- packed f32x2 helpers ----
__device__ __forceinline__ u64 pack2(float lo, float hi) {
    u64 r; asm("mov.b64 %0, {%1, %2};" : "=l"(r) : "f"(lo), "f"(hi)); return r;
}
__device__ __forceinline__ void unpack2(u64 v, float& lo, float& hi) {
    asm("mov.b64 {%0, %1}, %2;" : "=f"(lo), "=f"(hi) : "l"(v));
}
__device__ __forceinline__ u64 fma2(u64 a, u64 b, u64 c) {
    u64 d; asm("fma.rn.f32x2 %0, %1, %2, %3;" : "=l"(d) : "l"(a), "l"(b), "l"(c)); return d;
}
__device__ __forceinline__ u64 mul2(u64 a, u64 b) {
    u64 d; asm("mul.rn.f32x2 %0, %1, %2;" : "=l"(d) : "l"(a), "l"(b)); return d;
}
__device__ __forceinline__ u64 shfl64_w16(u64 v, int src) {
    return (u64)__shfl_sync(0xffffffffu, (long long)v, src, 16);
}
__device__ __forceinline__ u64 shfl64_xor16(u64 v) {
    return (u64)__shfl_xor_sync(0xffffffffu, (long long)v, 16, 32);
}
__device__ __forceinline__ float ex2f(float x) {
    float r; asm("ex2.approx.f32 %0, %1;" : "=f"(r) : "f"(x)); return r;
}
__device__ __forceinline__ float rcpf(float x) {
    float r; asm("rcp.approx.f32 %0, %1;" : "=f"(r) : "f"(x)); return r;
}
__device__ __forceinline__ u64 splat2(float v) { return pack2(v, v); }

// rational activation: r = 1/(1 + 2^(x*ka));  out = r*ks + kt
// sigmoid: ka=-log2e, ks=1, kt=0.  tanh: ka=-2log2e, ks=2, kt=-1.
__device__ __forceinline__ u64 act_r(u64 g, u64 ka, u64 ONE2) {
    u64 t = mul2(g, ka);
    float ta, tb; unpack2(t, ta, tb);
    u64 e = pack2(ex2f(ta), ex2f(tb));
    u64 d = fma2(e, ONE2, ONE2);
    float da, db; unpack2(d, da, db);
    return pack2(rcpf(da), rcpf(db));
}

__device__ __forceinline__ float gelu_exact(float v) {
    return 0.5f * v * (1.0f + erff(v * 0.70710678118654752f));
}

// ---------------------------------------------------------------------------
// Kernel 1: fused depthwise-conv(5,pad2)+BN+GELU  x2.  One block per (b,c) row.
// ---------------------------------------------------------------------------
__global__ void __launch_bounds__(256) prep_kernel(
    const float* __restrict__ x,
    const float* __restrict__ c1w, const float* __restrict__ c1b,
    const float* __restrict__ b1g, const float* __restrict__ b1b,
    const float* __restrict__ b1m, const float* __restrict__ b1v,
    const float* __restrict__ c2w, const float* __restrict__ c2b,
    const float* __restrict__ b2g, const float* __restrict__ b2b,
    const float* __restrict__ b2m, const float* __restrict__ b2v)
{
    __shared__ float xs[TT + 4];
    __shared__ float ys[TT + 4];

    const int chain = blockIdx.x;
    const int ch    = chain & 63;
    const int tid   = threadIdx.x;

    if (tid < 2) {
        xs[tid] = 0.0f; xs[TT + 2 + tid] = 0.0f;
        ys[tid] = 0.0f; ys[TT + 2 + tid] = 0.0f;
    }
    const float* xr = x + (size_t)chain * TT;
    for (int t = tid; t < TT; t += 256) xs[t + 2] = xr[t];

    const float w0 = c1w[ch * 5 + 0], w1 = c1w[ch * 5 + 1], w2 = c1w[ch * 5 + 2],
                w3 = c1w[ch * 5 + 3], w4 = c1w[ch * 5 + 4];
    const float s1 = b1g[ch] * rsqrtf(b1v[ch] + 1e-5f);
    const float d1 = (c1b[ch] - b1m[ch]) * s1 + b1b[ch];

    __syncthreads();
    for (int t = tid; t < TT; t += 256) {
        float a = xs[t] * w0;
        a = fmaf(xs[t + 1], w1, a);
        a = fmaf(xs[t + 2], w2, a);
        a = fmaf(xs[t + 3], w3, a);
        a = fmaf(xs[t + 4], w4, a);
        ys[t + 2] = gelu_exact(fmaf(a, s1, d1));
    }

    const float u0 = c2w[ch * 5 + 0], u1 = c2w[ch * 5 + 1], u2 = c2w[ch * 5 + 2],
                u3 = c2w[ch * 5 + 3], u4 = c2w[ch * 5 + 4];
    const float s2 = b2g[ch] * rsqrtf(b2v[ch] + 1e-5f);
    const float d2 = (c2b[ch] - b2m[ch]) * s2 + b2b[ch];

    __syncthreads();
    float* outr = g_seq + (size_t)chain * TT;
    for (int t = tid; t < TT; t += 256) {
        float a = ys[t] * u0;
        a = fmaf(ys[t + 1], u1, a);
        a = fmaf(ys[t + 2], u2, a);
        a = fmaf(ys[t + 3], u3, a);
        a = fmaf(ys[t + 4], u4, a);
        outr[t] = gelu_exact(fmaf(a, s2, d2));
    }
}

// ---------------------------------------------------------------------------
// Kernel 2: LSTM. Two same-direction chains packed per f32x2 lane (splat W).
// 32 lanes per packed unit: lanes 0-15 gates (i,f), lanes 16-31 gates (g,o).
// h broadcast via double-buffered shared memory; gate exchange via shfl_xor16.
// One warp = one packed unit = 2 chain-dirs.
// ---------------------------------------------------------------------------
__global__ void __launch_bounds__(128) lstm_kernel(
    const float* __restrict__ wihf, const float* __restrict__ whhf,
    const float* __restrict__ bihf, const float* __restrict__ bhhf,
    const float* __restrict__ wihr, const float* __restrict__ whhr,
    const float* __restrict__ bihr, const float* __restrict__ bhhr)
{
    __shared__ __align__(16) u64 hbuf[2][4][16];   // [parity][warp][unit]

    const int tid = threadIdx.x;
    const int wu  = tid >> 5;            // warp in block (0..3)
    const int l   = tid & 31;
    const int j   = l & 15;              // hidden unit
    const int hi  = l >> 4;              // 0: gates i,f   1: gates g,o

    const int pu  = blockIdx.x * 4 + wu; // 0..4095 packed units
    const bool bwd = (pu >= 2048);
    const int pairIdx = bwd ? pu - 2048 : pu;
    const int chainA  = 2 * pairIdx;
    const int chainB  = 2 * pairIdx + 1;

    const float* wih = bwd ? wihr : wihf;
    const float* whh = bwd ? whhr : whhf;
    const float* bih = bwd ? bihr : bihf;
    const float* bhh = bwd ? bhhr : bhhf;

    // this lane's two gate rows: k0 = 2*hi, k1 = 2*hi+1 (torch order i,f,g,o)
    const int r0 = (2 * hi) * 16 + j;
    const int r1 = (2 * hi + 1) * 16 + j;

    u64 W0[16], W1[16];
#pragma unroll
    for (int i = 0; i < 16; i++) {
        W0[i] = splat2(whh[r0 * 16 + i]);
        W1[i] = splat2(whh[r1 * 16 + i]);
    }
    const u64 wi0 = splat2(wih[r0]);
    const u64 wi1 = splat2(wih[r1]);
    const u64 bb0 = splat2(bih[r0] + bhh[r0]);
    const u64 bb1 = splat2(bih[r1] + bhh[r1]);

    const float L2E = 1.4426950408889634f;
    const u64 ONE2  = splat2(1.0f);
    const u64 ZERO2 = 0ull;
    // gate0: i (sigmoid) on low half, g (tanh) on high half
    const u64 KA0 = splat2(hi ? -2.0f * L2E : -L2E);
    const u64 KS0 = splat2(hi ? 2.0f : 1.0f);
    const u64 KT0 = splat2(hi ? -1.0f : 0.0f);
    // gate1: f / o — both sigmoid
    const u64 KA1 = splat2(-L2E);
    // tanh(c) constants
    const u64 KAC = splat2(-2.0f * L2E);
    const u64 TWO2  = splat2(2.0f);
    const u64 NONE2 = splat2(-1.0f);

    const float* seqA = g_seq + (size_t)chainA * TT;
    const float* seqB = g_seq + (size_t)chainB * TT;

    u64 h = 0ull, c = 0ull;

    for (int t0 = 0; t0 < TT; t0 += 16) {
        const int steps = (TT - t0) < 16 ? (TT - t0) : 16;
        const int tl    = t0 + j;
        u64 xv = 0ull;
        if (tl < TT) {
            const int idx = bwd ? (TT - 1 - tl) : tl;
            xv = pack2(seqA[idx], seqB[idx]);
        }

        for (int i = 0; i < steps; i++) {
            const int par = i & 1;
            // publish current h (both halves hold identical h; low half writes)
            if (hi == 0) hbuf[par][wu][j] = h;
            __syncwarp();

            const u64 xt = shfl64_w16(xv, i);
            u64 a0 = fma2(xt, wi0, bb0);
            u64 a1 = fma2(xt, wi1, bb1);
            u64 b0 = ZERO2, b1 = ZERO2;
            const ulonglong2* hb = (const ulonglong2*)&hbuf[par][wu][0];
#pragma unroll
            for (int ii = 0; ii < 8; ii++) {
                const ulonglong2 hp = hb[ii];        // broadcast LDS.128
                a0 = fma2(hp.x, W0[2 * ii], a0);
                b0 = fma2(hp.y, W0[2 * ii + 1], b0);
                a1 = fma2(hp.x, W1[2 * ii], a1);
                b1 = fma2(hp.y, W1[2 * ii + 1], b1);
            }
            const u64 g0 = fma2(b0, ONE2, a0);
            const u64 g1 = fma2(b1, ONE2, a1);

            // activations (identical code path on both halves; constants differ)
            const u64 rr0  = act_r(g0, KA0, ONE2);
            const u64 act0 = fma2(rr0, KS0, KT0);    // sigmoid(i) / tanh(g)
            const u64 act1 = act_r(g1, KA1, ONE2);   // sigmoid(f) / sigmoid(o)

            // exchange activated gates between halves
            const u64 ex0 = shfl64_xor16(act0);
            const u64 ex1 = shfl64_xor16(act1);
            const u64 ia = hi ? ex0 : act0;
            const u64 fa = hi ? ex1 : act1;
            const u64 ga = hi ? act0 : ex0;
            const u64 oa = hi ? act1 : ex1;

            c = fma2(fa, c, mul2(ia, ga));
            const u64 rc = act_r(c, KAC, ONE2);
            const u64 th = fma2(rc, TWO2, NONE2);    // tanh(c)
            h = mul2(oa, th);
        }
    }

    if (hi == 0) {
        float hA, hB; unpack2(h, hA, hB);
        const int off = bwd ? 16 : 0;
        g_feat[chainA * 32 + off + j] = hA;
        g_feat[chainB * 32 + off + j] = hB;
    }
}

// ---------------------------------------------------------------------------
// Kernel 3: out[n,e] = feat[n,:] . lin_w[e,:] + lin_b[e]
// ---------------------------------------------------------------------------
__global__ void __launch_bounds__(256) linear_kernel(
    const float* __restrict__ lw, const float* __restrict__ lb,
    float* __restrict__ out)
{
    const int idx = blockIdx.x * 256 + threadIdx.x;    // 131072 total
    const int n = idx >> 5;
    const int e = idx & 31;
    const float* f = g_feat + n * 32;
    const float* w = lw + e * 32;
    float acc = lb[e];
#pragma unroll
    for (int k = 0; k < 32; k++) acc = fmaf(f[k], w[k], acc);
    out[idx] = acc;
}

// ---------------------------------------------------------------------------
extern "C" void kernel_launch(void* const* d_in, const int* in_sizes, int n_in,
                              void* d_out, int out_size)
{
    const float* x      = (const float*)d_in[0];
    const float* c1w    = (const float*)d_in[1];
    const float* c1b    = (const float*)d_in[2];
    const float* b1g    = (const float*)d_in[3];
    const float* b1b    = (const float*)d_in[4];
    const float* b1m    = (const float*)d_in[5];
    const float* b1v    = (const float*)d_in[6];
    const float* c2w    = (const float*)d_in[7];
    const float* c2b    = (const float*)d_in[8];
    const float* b2g    = (const float*)d_in[9];
    const float* b2b    = (const float*)d_in[10];
    const float* b2m    = (const float*)d_in[11];
    const float* b2v    = (const float*)d_in[12];
    const float* wihf   = (const float*)d_in[13];
    const float* whhf   = (const float*)d_in[14];
    const float* bihf   = (const float*)d_in[15];
    const float* bhhf   = (const float*)d_in[16];
    const float* wihr   = (const float*)d_in[17];
    const float* whhr   = (const float*)d_in[18];
    const float* bihr   = (const float*)d_in[19];
    const float* bhhr   = (const float*)d_in[20];
    const float* lw     = (const float*)d_in[21];
    const float* lb     = (const float*)d_in[22];
    float* out = (float*)d_out;

    prep_kernel<<<NCH, 256>>>(x, c1w, c1b, b1g, b1b, b1m, b1v,
                              c2w, c2b, b2g, b2b, b2m, b2v);
    lstm_kernel<<<1024, 128>>>(wihf, whhf, bihf, bhhf,
                               wihr, whhr, bihr, bhhr);
    linear_kernel<<<(NCH * 32) / 256, 256>>>(lw, lb, out);
}

// round 5
// speedup vs baseline: 1.2419x; 1.2419x over previous
#include <cuda_runtime.h>
#include <cuda_fp16.h>

#define TT   1000
#define NCH  4096

// scratch (no cudaMalloc allowed)
__device__ float g_seq[NCH * TT];     // LSTM input, [chain][t], 16 MB
__device__ float g_feat[NCH * 32];    // [chain][ h_fwd(16) | h_bwd(16) ]

__device__ __forceinline__ float ex2f(float x) {
    float r; asm("ex2.approx.f32 %0, %1;" : "=f"(r) : "f"(x)); return r;
}
__device__ __forceinline__ float rcpf(float x) {
    float r; asm("rcp.approx.f32 %0, %1;" : "=f"(r) : "f"(x)); return r;
}
// sigmoid(x) = 1/(1+2^(-x*log2e));  tanh(x) = 2*sigmoid(2x)-1
__device__ __forceinline__ float sigf(float x) {
    return rcpf(1.0f + ex2f(x * -1.4426950408889634f));
}
__device__ __forceinline__ float tanhf_(float x) {
    return fmaf(2.0f, rcpf(1.0f + ex2f(x * -2.8853900817779268f)), -1.0f);
}
__device__ __forceinline__ void lstm_act(float gi, float gf, float gg, float go,
                                         float& c, float& h) {
    const float si = sigf(gi), sf = sigf(gf), so = sigf(go);
    const float tg = tanhf_(gg);
    c = fmaf(sf, c, si * tg);
    h = so * tanhf_(c);
}

// pack two floats as f16x2 (round-to-nearest), a in low half
__device__ __forceinline__ unsigned pack_h2(float a, float b) {
    __half2 v = __halves2half2(__float2half_rn(a), __float2half_rn(b));
    return *(unsigned*)&v;
}
// split h into (hi, lo) f16 pair packed in one u32: low16 = hi part
__device__ __forceinline__ unsigned split_pack(float h) {
    const __half hi = __float2half_rn(h);
    const float  hf = __half2float(hi);
    const __half lo = __float2half_rn(h - hf);
    __half2 v = __halves2half2(hi, lo);
    return *(unsigned*)&v;
}
__device__ __forceinline__ float f16_residual(float w) {
    return w - __half2float(__float2half_rn(w));
}

__device__ __forceinline__ void mma16816(float d[4], const unsigned a[4], const unsigned b[2]) {
    asm volatile("mma.sync.aligned.m16n8k16.row.col.f32.f16.f16.f32 "
                 "{%0,%1,%2,%3}, {%4,%5,%6,%7}, {%8,%9}, {%0,%1,%2,%3};"
                 : "+f"(d[0]), "+f"(d[1]), "+f"(d[2]), "+f"(d[3])
                 : "r"(a[0]), "r"(a[1]), "r"(a[2]), "r"(a[3]),
                   "r"(b[0]), "r"(b[1]));
}

__device__ __forceinline__ float gelu_exact(float v) {
    return 0.5f * v * (1.0f + erff(v * 0.70710678118654752f));
}

// ---------------------------------------------------------------------------
// Kernel 1: fused depthwise-conv(5,pad2)+BN+GELU x2. One block per (b,c) row.
// ---------------------------------------------------------------------------
__global__ void __launch_bounds__(256) prep_kernel(
    const float* __restrict__ x,
    const float* __restrict__ c1w, const float* __restrict__ c1b,
    const float* __restrict__ b1g, const float* __restrict__ b1b,
    const float* __restrict__ b1m, const float* __restrict__ b1v,
    const float* __restrict__ c2w, const float* __restrict__ c2b,
    const float* __restrict__ b2g, const float* __restrict__ b2b,
    const float* __restrict__ b2m, const float* __restrict__ b2v)
{
    __shared__ float xs[TT + 4];
    __shared__ float ys[TT + 4];

    const int chain = blockIdx.x;
    const int ch    = chain & 63;
    const int tid   = threadIdx.x;

    if (tid < 2) {
        xs[tid] = 0.0f; xs[TT + 2 + tid] = 0.0f;
        ys[tid] = 0.0f; ys[TT + 2 + tid] = 0.0f;
    }
    const float* xr = x + (size_t)chain * TT;
    for (int t = tid; t < TT; t += 256) xs[t + 2] = xr[t];

    const float w0 = c1w[ch * 5 + 0], w1 = c1w[ch * 5 + 1], w2 = c1w[ch * 5 + 2],
                w3 = c1w[ch * 5 + 3], w4 = c1w[ch * 5 + 4];
    const float s1 = b1g[ch] * rsqrtf(b1v[ch] + 1e-5f);
    const float d1 = (c1b[ch] - b1m[ch]) * s1 + b1b[ch];

    __syncthreads();
    for (int t = tid; t < TT; t += 256) {
        float a = xs[t] * w0;
        a = fmaf(xs[t + 1], w1, a);
        a = fmaf(xs[t + 2], w2, a);
        a = fmaf(xs[t + 3], w3, a);
        a = fmaf(xs[t + 4], w4, a);
        ys[t + 2] = gelu_exact(fmaf(a, s1, d1));
    }

    const float u0 = c2w[ch * 5 + 0], u1 = c2w[ch * 5 + 1], u2 = c2w[ch * 5 + 2],
                u3 = c2w[ch * 5 + 3], u4 = c2w[ch * 5 + 4];
    const float s2 = b2g[ch] * rsqrtf(b2v[ch] + 1e-5f);
    const float d2 = (c2b[ch] - b2m[ch]) * s2 + b2b[ch];

    __syncthreads();
    float* outr = g_seq + (size_t)chain * TT;
    for (int t = tid; t < TT; t += 256) {
        float a = ys[t] * u0;
        a = fmaf(ys[t + 1], u1, a);
        a = fmaf(ys[t + 2], u2, a);
        a = fmaf(ys[t + 3], u3, a);
        a = fmaf(ys[t + 4], u4, a);
        outr[t] = gelu_exact(fmaf(a, s2, d2));
    }
}

// ---------------------------------------------------------------------------
// Kernel 2: LSTM via warp-level HMMA. One warp = 4 same-direction chains.
// Gates(64x8) = W(64x16) . H(16x8), 4 M-tiles (one per torch gate i,f,g,o),
// fp16 split inputs + fp32 accumulate => ~1e-7 gate error.
//
// Lane roles:
//   MMA role (g = lane>>2, t = lane&3): standard m16n8k16 fragments.
//   ACT role (u = lane>>1, cp = lane&1): owns state (c,h) for
//       (unit u, local chains 2cp and 2cp+1).
// Gate redistribution D->ACT and h transposition ACT->B both via shfl.
// ---------------------------------------------------------------------------
__global__ void __launch_bounds__(128, 4) lstm_kernel(
    const float* __restrict__ wihf, const float* __restrict__ whhf,
    const float* __restrict__ bihf, const float* __restrict__ bhhf,
    const float* __restrict__ wihr, const float* __restrict__ whhr,
    const float* __restrict__ bihr, const float* __restrict__ bhhr)
{
    const int lane = threadIdx.x & 31;
    const int w    = blockIdx.x * 4 + (threadIdx.x >> 5);   // 0..2047
    const bool bwd = (w >= 1024);
    const int cb   = 4 * (bwd ? w - 1024 : w);              // chain base

    const float* wih = bwd ? wihr : wihf;
    const float* whh = bwd ? whhr : whhf;
    const float* bih = bwd ? bihr : bihf;
    const float* bhh = bwd ? bhhr : bhhf;

    const int g = lane >> 2;      // MMA group id
    const int t = lane & 3;       // MMA thread-in-group

    // ---- A fragments (W_hh split hi/lo), bias and w_ih per gate tile ----
    unsigned Ahi[4][4], Alo[4][4];
    float bb0[4], bb1[4], wi0[4], wi1[4];
#pragma unroll
    for (int m = 0; m < 4; m++) {
        const int r0 = m * 16 + g;
        const int r1 = r0 + 8;
        const float* W0 = whh + r0 * 16;
        const float* W1 = whh + r1 * 16;
        const float w00 = W0[2*t],   w01 = W0[2*t+1], w08 = W0[2*t+8], w09 = W0[2*t+9];
        const float w10 = W1[2*t],   w11 = W1[2*t+1], w18 = W1[2*t+8], w19 = W1[2*t+9];
        Ahi[m][0] = pack_h2(w00, w01);
        Ahi[m][1] = pack_h2(w10, w11);
        Ahi[m][2] = pack_h2(w08, w09);
        Ahi[m][3] = pack_h2(w18, w19);
        Alo[m][0] = pack_h2(f16_residual(w00), f16_residual(w01));
        Alo[m][1] = pack_h2(f16_residual(w10), f16_residual(w11));
        Alo[m][2] = pack_h2(f16_residual(w08), f16_residual(w09));
        Alo[m][3] = pack_h2(f16_residual(w18), f16_residual(w19));
        bb0[m] = bih[r0] + bhh[r0];
        bb1[m] = bih[r1] + bhh[r1];
        wi0[m] = wih[r0];
        wi1[m] = wih[r1];
    }

    // B-build source lanes: h(unit k, chain n) lives at lane 2k + (n>>1), slot n&1
    const int S0 = 4 * t + (g >> 1);        // k = 2t
    const int S1 = S0 + 2;                  // k = 2t+1
    const int S2 = S0 + 16;                 // k = 2t+8
    const int S3 = S0 + 18;                 // k = 2t+9
    const bool oddn = (g & 1);
    // Gate-redist source: quad (u = lane>>1, c pair = lane&1)
    const int SR = 4 * ((lane >> 1) & 7) + (lane & 1);
    const bool lowu = (lane < 16);          // u < 8

    // ---- state (ACT role): unit u = lane>>1, chains cb+2cp, cb+2cp+1 ----
    float c0 = 0.0f, h0 = 0.0f, c1 = 0.0f, h1 = 0.0f;
    unsigned hp0 = 0u, hp1 = 0u;            // split-packed h (f16 hi|lo)

    const int  s_lane = lane >> 2;          // staged step 0..7
    const int  c_lane = lane & 3;           // staged chain 0..3
    const float* seq_base = g_seq + (size_t)(cb + c_lane) * TT;

    for (int blk = 0; blk < 125; blk++) {
        const int tb = blk * 8;
        const int tg_ = tb + s_lane;
        const int xidx = bwd ? (TT - 1 - tg_) : tg_;
        const float xs = seq_base[xidx];    // x[chain c_lane][step s_lane]

#pragma unroll
        for (int s = 0; s < 8; s++) {
            // broadcast x for this step (real only for t<2)
            const float xA = __shfl_sync(0xffffffffu, xs, (2*t   + 4*s) & 31);
            const float xB = __shfl_sync(0xffffffffu, xs, (2*t+1 + 4*s) & 31);

            // D init: bias + w_ih * x
            float d[4][4];
#pragma unroll
            for (int m = 0; m < 4; m++) {
                d[m][0] = fmaf(wi0[m], xA, bb0[m]);
                d[m][1] = fmaf(wi0[m], xB, bb0[m]);
                d[m][2] = fmaf(wi1[m], xA, bb1[m]);
                d[m][3] = fmaf(wi1[m], xB, bb1[m]);
            }

            // build B fragments from previous h (split-packed)
            const unsigned q0a = __shfl_sync(0xffffffffu, hp0, S0);
            const unsigned q0b = __shfl_sync(0xffffffffu, hp1, S0);
            const unsigned q1a = __shfl_sync(0xffffffffu, hp0, S1);
            const unsigned q1b = __shfl_sync(0xffffffffu, hp1, S1);
            const unsigned q2a = __shfl_sync(0xffffffffu, hp0, S2);
            const unsigned q2b = __shfl_sync(0xffffffffu, hp1, S2);
            const unsigned q3a = __shfl_sync(0xffffffffu, hp0, S3);
            const unsigned q3b = __shfl_sync(0xffffffffu, hp1, S3);
            const unsigned p0 = oddn ? q0b : q0a;
            const unsigned p1 = oddn ? q1b : q1a;
            const unsigned p2 = oddn ? q2b : q2a;
            const unsigned p3 = oddn ? q3b : q3a;
            unsigned Bhi[2], Blo[2];
            Bhi[0] = __byte_perm(p0, p1, 0x5410);   // hi halves
            Bhi[1] = __byte_perm(p2, p3, 0x5410);
            Blo[0] = __byte_perm(p0, p1, 0x7632);   // lo halves
            Blo[1] = __byte_perm(p2, p3, 0x7632);

            // 12 HMMA: W_hi*h_hi + W_hi*h_lo + W_lo*h_hi (fp32 accumulate)
#pragma unroll
            for (int m = 0; m < 4; m++) {
                mma16816(d[m], Ahi[m], Bhi);
                mma16816(d[m], Ahi[m], Blo);
                mma16816(d[m], Alo[m], Bhi);
            }

            // redistribute gates: each lane collects its 2 quads
            float gA[4], gB[4];
#pragma unroll
            for (int m = 0; m < 4; m++) {
                const float va = __shfl_sync(0xffffffffu, d[m][0], SR);
                const float vb = __shfl_sync(0xffffffffu, d[m][1], SR);
                const float vc = __shfl_sync(0xffffffffu, d[m][2], SR);
                const float vd = __shfl_sync(0xffffffffu, d[m][3], SR);
                gA[m] = lowu ? va : vc;
                gB[m] = lowu ? vb : vd;
            }

            lstm_act(gA[0], gA[1], gA[2], gA[3], c0, h0);
            lstm_act(gB[0], gB[1], gB[2], gB[3], c1, h1);

            hp0 = split_pack(h0);
            hp1 = split_pack(h1);
        }
    }

    // write final h: lane owns (unit u = lane>>1, chains cb+2cp, cb+2cp+1)
    const int u  = lane >> 1;
    const int cp = lane & 1;
    const int off = bwd ? 16 : 0;
    g_feat[(cb + 2*cp)     * 32 + off + u] = h0;
    g_feat[(cb + 2*cp + 1) * 32 + off + u] = h1;
}

// ---------------------------------------------------------------------------
// Kernel 3: out[n,e] = feat[n,:] . lin_w[e,:] + lin_b[e]
// ---------------------------------------------------------------------------
__global__ void __launch_bounds__(256) linear_kernel(
    const float* __restrict__ lw, const float* __restrict__ lb,
    float* __restrict__ out)
{
    const int idx = blockIdx.x * 256 + threadIdx.x;    // 131072 total
    const int n = idx >> 5;
    const int e = idx & 31;
    const float* f = g_feat + n * 32;
    const float* wp = lw + e * 32;
    float acc = lb[e];
#pragma unroll
    for (int k = 0; k < 32; k++) acc = fmaf(f[k], wp[k], acc);
    out[idx] = acc;
}

// ---------------------------------------------------------------------------
extern "C" void kernel_launch(void* const* d_in, const int* in_sizes, int n_in,
                              void* d_out, int out_size)
{
    const float* x      = (const float*)d_in[0];
    const float* c1w    = (const float*)d_in[1];
    const float* c1b    = (const float*)d_in[2];
    const float* b1g    = (const float*)d_in[3];
    const float* b1b    = (const float*)d_in[4];
    const float* b1m    = (const float*)d_in[5];
    const float* b1v    = (const float*)d_in[6];
    const float* c2w    = (const float*)d_in[7];
    const float* c2b    = (const float*)d_in[8];
    const float* b2g    = (const float*)d_in[9];
    const float* b2b    = (const float*)d_in[10];
    const float* b2m    = (const float*)d_in[11];
    const float* b2v    = (const float*)d_in[12];
    const float* wihf   = (const float*)d_in[13];
    const float* whhf   = (const float*)d_in[14];
    const float* bihf   = (const float*)d_in[15];
    const float* bhhf   = (const float*)d_in[16];
    const float* wihr   = (const float*)d_in[17];
    const float* whhr   = (const float*)d_in[18];
    const float* bihr   = (const float*)d_in[19];
    const float* bhhr   = (const float*)d_in[20];
    const float* lw     = (const float*)d_in[21];
    const float* lb     = (const float*)d_in[22];
    float* out = (float*)d_out;

    prep_kernel<<<NCH, 256>>>(x, c1w, c1b, b1g, b1b, b1m, b1v,
                              c2w, c2b, b2g, b2b, b2m, b2v);
    lstm_kernel<<<512, 128>>>(wihf, whhf, bihf, bhhf,
                              wihr, whhr, bihr, bhhr);
    linear_kernel<<<(NCH * 32) / 256, 256>>>(lw, lb, out);
}